// round 5
// baseline (speedup 1.0000x reference)
#include <cuda_runtime.h>
#include <cuda_bf16.h>
#include <math.h>
#include <stdint.h>

#define MAXB 4096
#define MAXD 384
#define MAXC_PAD 13056   // 51*256

// ---- scratch (static device globals) ----
__device__ __align__(256) float g_Fm[MAXB * MAXD];
__device__ __align__(256) float g_Ft[MAXB * MAXD];
__device__ __align__(256) __nv_bfloat16 g_Fsb[MAXB * MAXD];
__device__ __align__(256) __nv_bfloat16 g_Wb[MAXC_PAD * MAXD];  // rows >= C stay zero
__device__ int   g_labm[MAXB];
__device__ int   g_posi[2][MAXB];
__device__ int   g_negi[2][MAXB];
__device__ float g_S[MAXB];
__device__ float g_T[MAXB];
__device__ float g_Z[MAXB];
__device__ float g_trip[2];

// ---------------- helpers ----------------
__device__ __forceinline__ unsigned int hmix(unsigned int x) {
    x ^= x >> 16; x *= 0x7feb352dU;
    x ^= x >> 15; x *= 0x846ca68bU;
    x ^= x >> 16;
    return x;
}

// exp(x), |x| < ~1, deg-8 Taylor (pure FMA, no MUFU)
__device__ __forceinline__ float fast_exp(float x) {
    float p = 2.4801587e-05f;
    p = fmaf(p, x, 1.9841270e-04f);
    p = fmaf(p, x, 1.3888889e-03f);
    p = fmaf(p, x, 8.3333334e-03f);
    p = fmaf(p, x, 4.1666668e-02f);
    p = fmaf(p, x, 1.6666667e-01f);
    p = fmaf(p, x, 0.5f);
    p = fmaf(p, x, 1.0f);
    p = fmaf(p, x, 1.0f);
    return p;
}

// ---------------- small kernels ----------------
__global__ void zero_kernel(int B) {
    int i = blockIdx.x * blockDim.x + threadIdx.x;
    if (i < B) { g_S[i] = 0.f; g_T[i] = 0.f; g_Z[i] = 0.f; }
    if (i < 2) g_trip[i] = 0.f;
}

__global__ void normalize_kernel(const float* __restrict__ f0,
                                 const float* __restrict__ f1,
                                 const float* __restrict__ f2,
                                 int B, int D) {
    const float* src = (blockIdx.y == 0) ? f0 : ((blockIdx.y == 1) ? f1 : f2);
    int row = blockIdx.x;
    const float* x = src + (size_t)row * D;
    float ss = 0.f;
    for (int d = threadIdx.x; d < D; d += blockDim.x) {
        float v = x[d];
        ss = fmaf(v, v, ss);
    }
    __shared__ float sh[128];
    sh[threadIdx.x] = ss;
    __syncthreads();
    for (int s = 64; s > 0; s >>= 1) {
        if (threadIdx.x < s) sh[threadIdx.x] += sh[threadIdx.x + s];
        __syncthreads();
    }
    __shared__ float inv;
    if (threadIdx.x == 0) {
        float nrm = fmaxf(sqrtf(sh[0]), 1e-12f);
        inv = 1.0f / nrm;
    }
    __syncthreads();
    if (blockIdx.y == 2) {
        __nv_bfloat16* y = g_Fsb + (size_t)row * D;
        for (int d = threadIdx.x; d < D; d += blockDim.x)
            y[d] = __float2bfloat16(x[d] * inv);
    } else {
        float* y = (blockIdx.y == 0 ? g_Fm : g_Ft) + (size_t)row * D;
        for (int d = threadIdx.x; d < D; d += blockDim.x) y[d] = x[d] * inv;
    }
}

__global__ void convw_kernel(const float* __restrict__ W, int total4) {
    int i = blockIdx.x * blockDim.x + threadIdx.x;
    if (i < total4) {
        float4 v = ((const float4*)W)[i];
        __nv_bfloat162 p0 = __floats2bfloat162_rn(v.x, v.y);
        __nv_bfloat162 p1 = __floats2bfloat162_rn(v.z, v.w);
        uint2 pk;
        pk.x = *(unsigned int*)&p0;
        pk.y = *(unsigned int*)&p1;
        *(uint2*)(g_Wb + (size_t)i * 4) = pk;
    }
}

// first-occurrence argmax per row; dual accumulator chains for MLP
__global__ void argmax_kernel(const float* __restrict__ M, int C) {
    int row = blockIdx.x;
    const float* x = M + (size_t)row * C;
    const float4* x4 = (const float4*)x;
    int C8 = C >> 3;
    float bv0 = -3.4e38f, bv1 = -3.4e38f;
    int bi0 = 0, bi1 = 0;
    for (int c8 = threadIdx.x; c8 < C8; c8 += blockDim.x) {
        float4 v = x4[2 * c8];
        float4 w = x4[2 * c8 + 1];
        int c = c8 << 3;
        if (v.x > bv0) { bv0 = v.x; bi0 = c; }
        if (v.y > bv0) { bv0 = v.y; bi0 = c + 1; }
        if (v.z > bv0) { bv0 = v.z; bi0 = c + 2; }
        if (v.w > bv0) { bv0 = v.w; bi0 = c + 3; }
        if (w.x > bv1) { bv1 = w.x; bi1 = c + 4; }
        if (w.y > bv1) { bv1 = w.y; bi1 = c + 5; }
        if (w.z > bv1) { bv1 = w.z; bi1 = c + 6; }
        if (w.w > bv1) { bv1 = w.w; bi1 = c + 7; }
    }
    for (int c = (C8 << 3) + threadIdx.x; c < C; c += blockDim.x) {
        float v = x[c];
        if (v > bv0) { bv0 = v; bi0 = c; }
    }
    float bv = bv0; int bi = bi0;
    if (bv1 > bv || (bv1 == bv && bi1 < bi)) { bv = bv1; bi = bi1; }
    __shared__ float sv[256];
    __shared__ int   si[256];
    sv[threadIdx.x] = bv; si[threadIdx.x] = bi;
    __syncthreads();
    for (int s = 128; s > 0; s >>= 1) {
        if (threadIdx.x < s) {
            float ov = sv[threadIdx.x + s];
            int   oi = si[threadIdx.x + s];
            if (ov > sv[threadIdx.x] || (ov == sv[threadIdx.x] && oi < si[threadIdx.x])) {
                sv[threadIdx.x] = ov; si[threadIdx.x] = oi;
            }
        }
        __syncthreads();
    }
    if (threadIdx.x == 0) g_labm[row] = si[0];
}

// Uniform pick of positive/negative via count-then-select (deterministic).
__global__ void pick2_kernel(int which, const int* __restrict__ ext_labels,
                             int use_internal, int B, int clipC, unsigned int salt) {
    __shared__ int slab[MAXB];
    __shared__ int sm_m[256], sm_n[256];
    __shared__ int s_pp, s_np;
    int i = blockIdx.x;
    int tid = threadIdx.x;
    if (tid == 0) { s_pp = -1; s_np = -1; }
    for (int j = tid; j < B; j += 256) {
        int l;
        if (use_internal) l = g_labm[j];
        else { l = ext_labels[j]; l = l < 0 ? 0 : (l >= clipC ? clipC - 1 : l); }
        slab[j] = l;
    }
    __syncthreads();
    int li = slab[i];
    int m = 0, n = 0;
    for (int j = tid; j < B; j += 256) {
        int lj = slab[j];
        if (lj == li) { if (j != i) m++; }
        else n++;
    }
    sm_m[tid] = m; sm_n[tid] = n;
    __syncthreads();
    for (int s = 1; s < 256; s <<= 1) {
        int am = (tid >= s) ? sm_m[tid - s] : 0;
        int an = (tid >= s) ? sm_n[tid - s] : 0;
        __syncthreads();
        sm_m[tid] += am; sm_n[tid] += an;
        __syncthreads();
    }
    int P  = sm_m[255];
    int Nn = sm_n[255];
    int basep = sm_m[tid] - m;
    int basen = sm_n[tid] - n;
    unsigned int rp = 0, rn = 0;
    if (P > 0)  rp = hmix(salt + 0x51u ^ ((unsigned int)i * 2654435761u)) % (unsigned int)P;
    if (Nn > 0) rn = hmix(salt + 0x77u ^ ((unsigned int)i * 2246822519u)) % (unsigned int)Nn;
    if (P > 0 && (unsigned)basep <= rp && rp < (unsigned)(basep + m)) {
        int cnt = basep;
        for (int j = tid; j < B; j += 256) {
            int lj = slab[j];
            if (lj == li && j != i) {
                if ((unsigned)cnt == rp) s_pp = j;
                cnt++;
            }
        }
    }
    if (Nn > 0 && (unsigned)basen <= rn && rn < (unsigned)(basen + n)) {
        int cnt = basen;
        for (int j = tid; j < B; j += 256) {
            if (slab[j] != li) {
                if ((unsigned)cnt == rn) s_np = j;
                cnt++;
            }
        }
    }
    __syncthreads();
    if (tid == 0) {
        int p = s_pp;
        if (P == 0) p = (int)(hmix(salt ^ ((unsigned int)i * 2654435761u) ^ 0xA5A5u) % (unsigned int)B);
        int nidx = s_np;
        if (Nn == 0) nidx = (int)(hmix(salt ^ ((unsigned int)i * 2246822519u) ^ 0x5A5Au) % (unsigned int)B);
        g_posi[which][i] = p;
        g_negi[which][i] = nidx;
    }
}

__global__ void triplet_kernel(int B, int D) {
    int which = blockIdx.y;
    int i = blockIdx.x;
    const float* F = which ? g_Ft : g_Fm;
    int p = g_posi[which][i];
    int n = g_negi[which][i];
    const float* a  = F + (size_t)i * D;
    const float* pp = F + (size_t)p * D;
    const float* nn = F + (size_t)n * D;
    float sap = 0.f, san = 0.f;
    for (int d = threadIdx.x; d < D; d += blockDim.x) {
        float da = a[d] - pp[d] + 1e-6f;
        float dn = a[d] - nn[d] + 1e-6f;
        sap = fmaf(da, da, sap);
        san = fmaf(dn, dn, san);
    }
    __shared__ float s1[128], s2[128];
    s1[threadIdx.x] = sap; s2[threadIdx.x] = san;
    __syncthreads();
    for (int s = 64; s > 0; s >>= 1) {
        if (threadIdx.x < s) { s1[threadIdx.x] += s1[threadIdx.x + s]; s2[threadIdx.x] += s2[threadIdx.x + s]; }
        __syncthreads();
    }
    if (threadIdx.x == 0) {
        float v = sqrtf(s1[0]) - sqrtf(s2[0]) + 0.3f;
        if (v > 0.f) atomicAdd(&g_trip[which], v);
    }
}

// ---------------- bf16 HMMA GEMM 128x256 + fused CE epilogue ----------------
#define BM 128
#define BN 256
#define BK 32
#define LDST 40   // smem row stride in bf16 (80B)

#define SM_A_ELEMS (BM * LDST)            // 5120 bf16 per stage
#define SM_B_ELEMS (BN * LDST)            // 10240 bf16 per stage
#define OFF_A  0
#define OFF_B  (2 * SM_A_ELEMS * 2)                    // after A stages (bytes)
#define OFF_SS (OFF_B + 2 * SM_B_ELEMS * 2)            // float sS[BM]
#define OFF_ST (OFF_SS + BM * 4)
#define OFF_BIAS (OFF_ST + BM * 4)                     // float sBias[BN]
#define GEMM_SMEM (OFF_BIAS + BN * 4)

__device__ __forceinline__ void gemm_load_stage2(
    __nv_bfloat16* As, __nv_bfloat16* Bs,
    const __nv_bfloat16* Ag, const __nv_bfloat16* Bg,
    int tid, int k0, int D)
{
#pragma unroll
    for (int it = 0; it < 2; it++) {
        int cid = tid + it * 256;
        int r = cid >> 2;
        int kk = (cid & 3) << 3;
        unsigned int sa = (unsigned int)__cvta_generic_to_shared(As + r * LDST + kk);
        asm volatile("cp.async.cg.shared.global [%0], [%1], 16;\n"
                     :: "r"(sa), "l"(Ag + (size_t)r * D + k0 + kk));
    }
#pragma unroll
    for (int it = 0; it < 4; it++) {
        int cid = tid + it * 256;
        int r = cid >> 2;
        int kk = (cid & 3) << 3;
        unsigned int sb = (unsigned int)__cvta_generic_to_shared(Bs + r * LDST + kk);
        asm volatile("cp.async.cg.shared.global [%0], [%1], 16;\n"
                     :: "r"(sb), "l"(Bg + (size_t)r * D + k0 + kk));
    }
    asm volatile("cp.async.commit_group;\n" ::: "memory");
}

__global__ __launch_bounds__(256, 1)
void ce_gemm_mma(const float* __restrict__ bias, const int* __restrict__ labels,
                 int B, int C, int D) {
    extern __shared__ char dsm[];
    __nv_bfloat16* Asm = (__nv_bfloat16*)(dsm + OFF_A);
    __nv_bfloat16* Bsm = (__nv_bfloat16*)(dsm + OFF_B);
    float* sS   = (float*)(dsm + OFF_SS);
    float* sT   = (float*)(dsm + OFF_ST);
    float* sBias = (float*)(dsm + OFF_BIAS);

    const int tid  = threadIdx.x;
    const int lane = tid & 31;
    const int warp = tid >> 5;
    const int wm = (warp >> 2) * 64;   // 2 warps in M
    const int wn = (warp & 3) * 64;    // 4 warps in N
    const int rowBase = blockIdx.y * BM;
    const int colBase = blockIdx.x * BN;

    if (tid < BM) { sS[tid] = 0.f; sT[tid] = 0.f; }
    {
        int c = colBase + tid;                  // one store per thread: BN == blockDim
        sBias[tid] = (c < C) ? bias[c] : 0.f;
    }

    float acc[4][8][4];
#pragma unroll
    for (int a = 0; a < 4; a++)
#pragma unroll
        for (int b = 0; b < 8; b++)
#pragma unroll
            for (int c = 0; c < 4; c++) acc[a][b][c] = 0.f;

    const __nv_bfloat16* Ag = g_Fsb + (size_t)rowBase * D;
    const __nv_bfloat16* Bg = g_Wb  + (size_t)colBase * D;

    const int NK = D / BK;  // 12
    gemm_load_stage2(Asm, Bsm, Ag, Bg, tid, 0, D);

    for (int it = 0; it < NK; ++it) {
        if (it + 1 < NK) {
            gemm_load_stage2(Asm + ((it + 1) & 1) * SM_A_ELEMS,
                             Bsm + ((it + 1) & 1) * SM_B_ELEMS,
                             Ag, Bg, tid, (it + 1) * BK, D);
            asm volatile("cp.async.wait_group 1;\n" ::: "memory");
        } else {
            asm volatile("cp.async.wait_group 0;\n" ::: "memory");
        }
        __syncthreads();

        const __nv_bfloat16* Ab = Asm + (it & 1) * SM_A_ELEMS;
        const __nv_bfloat16* Bb = Bsm + (it & 1) * SM_B_ELEMS;
#pragma unroll
        for (int ks = 0; ks < BK; ks += 16) {
            unsigned int af[4][4];
#pragma unroll
            for (int mt = 0; mt < 4; mt++) {
                int row = wm + mt * 16 + (lane & 15);
                int col = ks + ((lane >> 4) << 3);
                unsigned int addr = (unsigned int)__cvta_generic_to_shared(Ab + row * LDST + col);
                asm volatile("ldmatrix.sync.aligned.m8n8.x4.shared.b16 {%0,%1,%2,%3}, [%4];\n"
                             : "=r"(af[mt][0]), "=r"(af[mt][1]), "=r"(af[mt][2]), "=r"(af[mt][3])
                             : "r"(addr));
            }
            unsigned int bfg[8][2];
#pragma unroll
            for (int nt = 0; nt < 8; nt += 2) {
                // x4 over 16 n-rows x 16 k-cols:
                // m0=(rows nt, ks) m1=(rows nt+1, ks) m2=(rows nt, ks+8) m3=(rows nt+1, ks+8)
                int row = wn + nt * 8 + (lane & 15);
                int col = ks + ((lane >> 4) << 3);
                unsigned int addr = (unsigned int)__cvta_generic_to_shared(Bb + row * LDST + col);
                asm volatile("ldmatrix.sync.aligned.m8n8.x4.shared.b16 {%0,%1,%2,%3}, [%4];\n"
                             : "=r"(bfg[nt][0]), "=r"(bfg[nt + 1][0]),
                               "=r"(bfg[nt][1]), "=r"(bfg[nt + 1][1])
                             : "r"(addr));
            }
#pragma unroll
            for (int mt = 0; mt < 4; mt++)
#pragma unroll
                for (int nt = 0; nt < 8; nt++) {
                    asm volatile(
                        "mma.sync.aligned.m16n8k16.row.col.f32.bf16.bf16.f32 "
                        "{%0,%1,%2,%3}, {%4,%5,%6,%7}, {%8,%9}, {%0,%1,%2,%3};\n"
                        : "+f"(acc[mt][nt][0]), "+f"(acc[mt][nt][1]),
                          "+f"(acc[mt][nt][2]), "+f"(acc[mt][nt][3])
                        : "r"(af[mt][0]), "r"(af[mt][1]), "r"(af[mt][2]), "r"(af[mt][3]),
                          "r"(bfg[nt][0]), "r"(bfg[nt][1]));
                }
        }
        __syncthreads();
    }

    // ---- fused CE epilogue in accumulator layout ----
#pragma unroll
    for (int mt = 0; mt < 4; mt++) {
        int r0loc = wm + mt * 16 + (lane >> 2);
        int r1loc = r0loc + 8;
        int gr0 = rowBase + r0loc;
        int gr1 = rowBase + r1loc;
        int lab0 = labels[gr0]; lab0 = lab0 < 0 ? 0 : (lab0 >= C ? C - 1 : lab0);
        int lab1 = labels[gr1]; lab1 = lab1 < 0 ? 0 : (lab1 >= C ? C - 1 : lab1);
        float s0 = 0.f, t0 = 0.f, s1 = 0.f, t1 = 0.f;
#pragma unroll
        for (int nt = 0; nt < 8; nt++) {
            int c0loc = wn + nt * 8 + ((lane & 3) << 1);
            int c0 = colBase + c0loc;
            int c1 = c0 + 1;
            float bv0 = sBias[c0loc];
            float bv1 = sBias[c0loc + 1];
            if (c0 < C) {
                float l00 = acc[mt][nt][0] + bv0;
                float l10 = acc[mt][nt][2] + bv0;
                t0 += l00; s0 += fast_exp(l00);
                t1 += l10; s1 += fast_exp(l10);
                if (c0 == lab0) g_Z[gr0] = l00;
                if (c0 == lab1) g_Z[gr1] = l10;
            }
            if (c1 < C) {
                float l01 = acc[mt][nt][1] + bv1;
                float l11 = acc[mt][nt][3] + bv1;
                t0 += l01; s0 += fast_exp(l01);
                t1 += l11; s1 += fast_exp(l11);
                if (c1 == lab0) g_Z[gr0] = l01;
                if (c1 == lab1) g_Z[gr1] = l11;
            }
        }
        s0 += __shfl_xor_sync(0xffffffffu, s0, 1);
        s0 += __shfl_xor_sync(0xffffffffu, s0, 2);
        t0 += __shfl_xor_sync(0xffffffffu, t0, 1);
        t0 += __shfl_xor_sync(0xffffffffu, t0, 2);
        s1 += __shfl_xor_sync(0xffffffffu, s1, 1);
        s1 += __shfl_xor_sync(0xffffffffu, s1, 2);
        t1 += __shfl_xor_sync(0xffffffffu, t1, 1);
        t1 += __shfl_xor_sync(0xffffffffu, t1, 2);
        if ((lane & 3) == 0) {
            atomicAdd(&sS[r0loc], s0);
            atomicAdd(&sT[r0loc], t0);
            atomicAdd(&sS[r1loc], s1);
            atomicAdd(&sT[r1loc], t1);
        }
    }
    __syncthreads();
    if (tid < BM) {
        atomicAdd(&g_S[rowBase + tid], sS[tid]);
        atomicAdd(&g_T[rowBase + tid], sT[tid]);
    }
}

// total = moco + 0.5*(trip_m + trip_t)/B + mean_i[ log(S_i) - 0.9*Z_i - 0.1*T_i/C ]
__global__ void final_kernel(const float* __restrict__ moco, int B, int C,
                             float* __restrict__ out) {
    __shared__ double sh[256];
    double loc = 0.0;
    for (int i = threadIdx.x; i < B; i += 256) {
        loc += (double)logf(g_S[i]) - 0.9 * (double)g_Z[i]
             - (0.1 / (double)C) * (double)g_T[i];
    }
    sh[threadIdx.x] = loc;
    __syncthreads();
    for (int s = 128; s > 0; s >>= 1) {
        if (threadIdx.x < s) sh[threadIdx.x] += sh[threadIdx.x + s];
        __syncthreads();
    }
    if (threadIdx.x == 0) {
        double ce = sh[0] / (double)B;
        double total = (double)moco[0]
                     + 0.5 * ((double)g_trip[0] / (double)B + (double)g_trip[1] / (double)B)
                     + ce;
        out[0] = (float)total;
    }
}

// ---------------- launch ----------------
extern "C" void kernel_launch(void* const* d_in, const int* in_sizes, int n_in,
                              void* d_out, int out_size) {
    const float* F_mixed       = (const float*)d_in[0];
    const float* F_target      = (const float*)d_in[1];
    const float* F_source      = (const float*)d_in[2];
    const float* mixed_labels  = (const float*)d_in[3];
    const int*   pseudo_labels = (const int*)d_in[4];
    const int*   source_labels = (const int*)d_in[5];
    const float* moco = (const float*)d_in[7];
    const float* W    = (const float*)d_in[8];
    const float* b    = (const float*)d_in[9];
    float* out = (float*)d_out;

    int B = in_sizes[4];
    int C = in_sizes[9];
    int D = in_sizes[0] / B;

    cudaFuncSetAttribute(ce_gemm_mma, cudaFuncAttributeMaxDynamicSharedMemorySize, GEMM_SMEM);

    zero_kernel<<<(B + 255) / 256, 256>>>(B);
    normalize_kernel<<<dim3(B, 3), 128>>>(F_mixed, F_target, F_source, B, D);
    int total4 = (C * D) / 4;
    convw_kernel<<<(total4 + 255) / 256, 256>>>(W, total4);
    argmax_kernel<<<B, 256>>>(mixed_labels, C);
    pick2_kernel<<<B, 256>>>(0, (const int*)0, 1, B, C, 12345u);
    pick2_kernel<<<B, 256>>>(1, pseudo_labels, 0, B, C, 777777u);
    triplet_kernel<<<dim3(B, 2), 128>>>(B, D);
    dim3 gg((C + BN - 1) / BN, (B + BM - 1) / BM);
    ce_gemm_mma<<<gg, 256, GEMM_SMEM>>>(b, source_labels, B, C, D);
    final_kernel<<<1, 256>>>(moco, B, C, out);
    (void)n_in; (void)out_size;
}

// round 6
// speedup vs baseline: 1.1870x; 1.1870x over previous
#include <cuda_runtime.h>
#include <cuda_bf16.h>
#include <math.h>
#include <stdint.h>

#define MAXB 4096
#define MAXD 384
#define MAXC_PAD 13056

// ---- scratch (static device globals) ----
__device__ __align__(256) float g_Fm[MAXB * MAXD];
__device__ __align__(256) float g_Ft[MAXB * MAXD];
__device__ __align__(256) __nv_bfloat16 g_Fsb[MAXB * MAXD];
__device__ __align__(256) __nv_bfloat16 g_Wb[MAXC_PAD * MAXD];  // rows >= C stay zero
__device__ int   g_labm[MAXB];
__device__ int   g_posi[2][MAXB];
__device__ int   g_negi[2][MAXB];
__device__ float g_S[MAXB];
__device__ float g_T[MAXB];
__device__ float g_Z[MAXB];
__device__ float g_trip[2];

// ---------------- helpers ----------------
__device__ __forceinline__ unsigned int hmix(unsigned int x) {
    x ^= x >> 16; x *= 0x7feb352dU;
    x ^= x >> 15; x *= 0x846ca68bU;
    x ^= x >> 16;
    return x;
}

// exp(x), |x| < ~1, deg-8 Taylor (pure FMA, no MUFU)
__device__ __forceinline__ float fast_exp(float x) {
    float p = 2.4801587e-05f;
    p = fmaf(p, x, 1.9841270e-04f);
    p = fmaf(p, x, 1.3888889e-03f);
    p = fmaf(p, x, 8.3333334e-03f);
    p = fmaf(p, x, 4.1666668e-02f);
    p = fmaf(p, x, 1.6666667e-01f);
    p = fmaf(p, x, 0.5f);
    p = fmaf(p, x, 1.0f);
    p = fmaf(p, x, 1.0f);
    return p;
}

// ---------------- small kernels ----------------
__global__ void zero_kernel(int B) {
    int i = blockIdx.x * blockDim.x + threadIdx.x;
    if (i < B) { g_S[i] = 0.f; g_T[i] = 0.f; g_Z[i] = 0.f; }
    if (i < 2) g_trip[i] = 0.f;
}

__global__ void normalize_kernel(const float* __restrict__ f0,
                                 const float* __restrict__ f1,
                                 const float* __restrict__ f2,
                                 int B, int D) {
    const float* src = (blockIdx.y == 0) ? f0 : ((blockIdx.y == 1) ? f1 : f2);
    int row = blockIdx.x;
    const float* x = src + (size_t)row * D;
    float ss = 0.f;
    for (int d = threadIdx.x; d < D; d += blockDim.x) {
        float v = x[d];
        ss = fmaf(v, v, ss);
    }
    __shared__ float sh[128];
    sh[threadIdx.x] = ss;
    __syncthreads();
    for (int s = 64; s > 0; s >>= 1) {
        if (threadIdx.x < s) sh[threadIdx.x] += sh[threadIdx.x + s];
        __syncthreads();
    }
    __shared__ float inv;
    if (threadIdx.x == 0) {
        float nrm = fmaxf(sqrtf(sh[0]), 1e-12f);
        inv = 1.0f / nrm;
    }
    __syncthreads();
    if (blockIdx.y == 2) {
        __nv_bfloat16* y = g_Fsb + (size_t)row * D;
        for (int d = threadIdx.x; d < D; d += blockDim.x)
            y[d] = __float2bfloat16(x[d] * inv);
    } else {
        float* y = (blockIdx.y == 0 ? g_Fm : g_Ft) + (size_t)row * D;
        for (int d = threadIdx.x; d < D; d += blockDim.x) y[d] = x[d] * inv;
    }
}

__global__ void convw_kernel(const float* __restrict__ W, int total4) {
    int i = blockIdx.x * blockDim.x + threadIdx.x;
    if (i < total4) {
        float4 v = ((const float4*)W)[i];
        __nv_bfloat162 p0 = __floats2bfloat162_rn(v.x, v.y);
        __nv_bfloat162 p1 = __floats2bfloat162_rn(v.z, v.w);
        uint2 pk;
        pk.x = *(unsigned int*)&p0;
        pk.y = *(unsigned int*)&p1;
        *(uint2*)(g_Wb + (size_t)i * 4) = pk;
    }
}

// first-occurrence argmax per row; 4 accumulator chains for deeper MLP
__global__ void argmax_kernel(const float* __restrict__ M, int C) {
    int row = blockIdx.x;
    const float* x = M + (size_t)row * C;
    const float4* x4 = (const float4*)x;
    int C16 = C >> 4;
    float bv0 = -3.4e38f, bv1 = -3.4e38f, bv2 = -3.4e38f, bv3 = -3.4e38f;
    int bi0 = 0, bi1 = 0, bi2 = 0, bi3 = 0;
    for (int c16 = threadIdx.x; c16 < C16; c16 += blockDim.x) {
        float4 v0 = x4[4 * c16 + 0];
        float4 v1 = x4[4 * c16 + 1];
        float4 v2 = x4[4 * c16 + 2];
        float4 v3 = x4[4 * c16 + 3];
        int c = c16 << 4;
        if (v0.x > bv0) { bv0 = v0.x; bi0 = c; }
        if (v0.y > bv0) { bv0 = v0.y; bi0 = c + 1; }
        if (v0.z > bv0) { bv0 = v0.z; bi0 = c + 2; }
        if (v0.w > bv0) { bv0 = v0.w; bi0 = c + 3; }
        if (v1.x > bv1) { bv1 = v1.x; bi1 = c + 4; }
        if (v1.y > bv1) { bv1 = v1.y; bi1 = c + 5; }
        if (v1.z > bv1) { bv1 = v1.z; bi1 = c + 6; }
        if (v1.w > bv1) { bv1 = v1.w; bi1 = c + 7; }
        if (v2.x > bv2) { bv2 = v2.x; bi2 = c + 8; }
        if (v2.y > bv2) { bv2 = v2.y; bi2 = c + 9; }
        if (v2.z > bv2) { bv2 = v2.z; bi2 = c + 10; }
        if (v2.w > bv2) { bv2 = v2.w; bi2 = c + 11; }
        if (v3.x > bv3) { bv3 = v3.x; bi3 = c + 12; }
        if (v3.y > bv3) { bv3 = v3.y; bi3 = c + 13; }
        if (v3.z > bv3) { bv3 = v3.z; bi3 = c + 14; }
        if (v3.w > bv3) { bv3 = v3.w; bi3 = c + 15; }
    }
    for (int c = (C16 << 4) + threadIdx.x; c < C; c += blockDim.x) {
        float v = x[c];
        if (v > bv0) { bv0 = v; bi0 = c; }
    }
    // merge chains, first-occurrence tie-break (lower index wins on equal)
    float bv = bv0; int bi = bi0;
    if (bv1 > bv || (bv1 == bv && bi1 < bi)) { bv = bv1; bi = bi1; }
    if (bv2 > bv || (bv2 == bv && bi2 < bi)) { bv = bv2; bi = bi2; }
    if (bv3 > bv || (bv3 == bv && bi3 < bi)) { bv = bv3; bi = bi3; }
    __shared__ float sv[256];
    __shared__ int   si[256];
    sv[threadIdx.x] = bv; si[threadIdx.x] = bi;
    __syncthreads();
    for (int s = 128; s > 0; s >>= 1) {
        if (threadIdx.x < s) {
            float ov = sv[threadIdx.x + s];
            int   oi = si[threadIdx.x + s];
            if (ov > sv[threadIdx.x] || (ov == sv[threadIdx.x] && oi < si[threadIdx.x])) {
                sv[threadIdx.x] = ov; si[threadIdx.x] = oi;
            }
        }
        __syncthreads();
    }
    if (threadIdx.x == 0) g_labm[row] = si[0];
}

// Uniform pick of positive/negative via count-then-select (deterministic).
__global__ void pick2_kernel(int which, const int* __restrict__ ext_labels,
                             int use_internal, int B, int clipC, unsigned int salt) {
    __shared__ int slab[MAXB];
    __shared__ int sm_m[256], sm_n[256];
    __shared__ int s_pp, s_np;
    int i = blockIdx.x;
    int tid = threadIdx.x;
    if (tid == 0) { s_pp = -1; s_np = -1; }
    for (int j = tid; j < B; j += 256) {
        int l;
        if (use_internal) l = g_labm[j];
        else { l = ext_labels[j]; l = l < 0 ? 0 : (l >= clipC ? clipC - 1 : l); }
        slab[j] = l;
    }
    __syncthreads();
    int li = slab[i];
    int m = 0, n = 0;
    for (int j = tid; j < B; j += 256) {
        int lj = slab[j];
        if (lj == li) { if (j != i) m++; }
        else n++;
    }
    sm_m[tid] = m; sm_n[tid] = n;
    __syncthreads();
    for (int s = 1; s < 256; s <<= 1) {
        int am = (tid >= s) ? sm_m[tid - s] : 0;
        int an = (tid >= s) ? sm_n[tid - s] : 0;
        __syncthreads();
        sm_m[tid] += am; sm_n[tid] += an;
        __syncthreads();
    }
    int P  = sm_m[255];
    int Nn = sm_n[255];
    int basep = sm_m[tid] - m;
    int basen = sm_n[tid] - n;
    unsigned int rp = 0, rn = 0;
    if (P > 0)  rp = hmix(salt + 0x51u ^ ((unsigned int)i * 2654435761u)) % (unsigned int)P;
    if (Nn > 0) rn = hmix(salt + 0x77u ^ ((unsigned int)i * 2246822519u)) % (unsigned int)Nn;
    if (P > 0 && (unsigned)basep <= rp && rp < (unsigned)(basep + m)) {
        int cnt = basep;
        for (int j = tid; j < B; j += 256) {
            int lj = slab[j];
            if (lj == li && j != i) {
                if ((unsigned)cnt == rp) s_pp = j;
                cnt++;
            }
        }
    }
    if (Nn > 0 && (unsigned)basen <= rn && rn < (unsigned)(basen + n)) {
        int cnt = basen;
        for (int j = tid; j < B; j += 256) {
            if (slab[j] != li) {
                if ((unsigned)cnt == rn) s_np = j;
                cnt++;
            }
        }
    }
    __syncthreads();
    if (tid == 0) {
        int p = s_pp;
        if (P == 0) p = (int)(hmix(salt ^ ((unsigned int)i * 2654435761u) ^ 0xA5A5u) % (unsigned int)B);
        int nidx = s_np;
        if (Nn == 0) nidx = (int)(hmix(salt ^ ((unsigned int)i * 2246822519u) ^ 0x5A5Au) % (unsigned int)B);
        g_posi[which][i] = p;
        g_negi[which][i] = nidx;
    }
}

__global__ void triplet_kernel(int B, int D) {
    int which = blockIdx.y;
    int i = blockIdx.x;
    const float* F = which ? g_Ft : g_Fm;
    int p = g_posi[which][i];
    int n = g_negi[which][i];
    const float* a  = F + (size_t)i * D;
    const float* pp = F + (size_t)p * D;
    const float* nn = F + (size_t)n * D;
    float sap = 0.f, san = 0.f;
    for (int d = threadIdx.x; d < D; d += blockDim.x) {
        float da = a[d] - pp[d] + 1e-6f;
        float dn = a[d] - nn[d] + 1e-6f;
        sap = fmaf(da, da, sap);
        san = fmaf(dn, dn, san);
    }
    __shared__ float s1[128], s2[128];
    s1[threadIdx.x] = sap; s2[threadIdx.x] = san;
    __syncthreads();
    for (int s = 64; s > 0; s >>= 1) {
        if (threadIdx.x < s) { s1[threadIdx.x] += s1[threadIdx.x + s]; s2[threadIdx.x] += s2[threadIdx.x + s]; }
        __syncthreads();
    }
    if (threadIdx.x == 0) {
        float v = sqrtf(s1[0]) - sqrtf(s2[0]) + 0.3f;
        if (v > 0.f) atomicAdd(&g_trip[which], v);
    }
}

// ------- bf16 HMMA GEMM 128x128, 4 warps (64x64 warp tile), BK=64 -------
#define BM 128
#define BN 128
#define BK 64
#define LDST 72   // smem row stride in bf16 (144B): conflict-free ldmatrix

#define SM_AB_ELEMS ((BM + BN) * LDST)               // per-stage elems (A then B)
#define STAGE_BYTES (SM_AB_ELEMS * 2)                // 36864 B
#define OFF_SS   (2 * STAGE_BYTES)
#define OFF_ST   (OFF_SS + BM * 4)
#define OFF_BIAS (OFF_ST + BM * 4)
#define GEMM_SMEM (OFF_BIAS + BN * 4)                // ~75.3 KB

__device__ __forceinline__ void gemm_load_stage(
    __nv_bfloat16* stage,
    const __nv_bfloat16* Ag, const __nv_bfloat16* Bg,
    int tid, int k0, int D)
{
    // 256 rows (128 A + 128 B) x 8 chunks of 16B = 2048 cp.async; 16/thread
#pragma unroll
    for (int t = 0; t < 16; t++) {
        int cid = tid + t * 128;
        int row = cid >> 3;
        int c = cid & 7;
        const __nv_bfloat16* src = (row < BM)
            ? (Ag + (size_t)row * D + k0 + c * 8)
            : (Bg + (size_t)(row - BM) * D + k0 + c * 8);
        unsigned int dst = (unsigned int)__cvta_generic_to_shared(stage + row * LDST + c * 8);
        asm volatile("cp.async.cg.shared.global [%0], [%1], 16;\n" :: "r"(dst), "l"(src));
    }
    asm volatile("cp.async.commit_group;\n" ::: "memory");
}

__global__ __launch_bounds__(128)
void ce_gemm_mma(const float* __restrict__ bias, const int* __restrict__ labels,
                 int B, int C, int D) {
    extern __shared__ char dsm[];
    __nv_bfloat16* stage0 = (__nv_bfloat16*)dsm;
    float* sS    = (float*)(dsm + OFF_SS);
    float* sT    = (float*)(dsm + OFF_ST);
    float* sBias = (float*)(dsm + OFF_BIAS);

    const int tid  = threadIdx.x;
    const int lane = tid & 31;
    const int warp = tid >> 5;
    const int wm = (warp >> 1) * 64;   // 2 warps in M
    const int wn = (warp & 1) * 64;    // 2 warps in N
    const int rowBase = blockIdx.y * BM;
    const int colBase = blockIdx.x * BN;

    sS[tid] = 0.f; sT[tid] = 0.f;
    {
        int c = colBase + tid;
        sBias[tid] = (c < C) ? bias[c] : 0.f;
    }

    float acc[4][8][4];
#pragma unroll
    for (int a = 0; a < 4; a++)
#pragma unroll
        for (int b = 0; b < 8; b++)
#pragma unroll
            for (int c = 0; c < 4; c++) acc[a][b][c] = 0.f;

    const __nv_bfloat16* Ag = g_Fsb + (size_t)rowBase * D;
    const __nv_bfloat16* Bg = g_Wb  + (size_t)colBase * D;

    const int NK = D / BK;  // 6
    gemm_load_stage(stage0, Ag, Bg, tid, 0, D);

    for (int it = 0; it < NK; ++it) {
        asm volatile("cp.async.wait_group 0;\n" ::: "memory");
        __syncthreads();
        // prefetch next chunk into the other stage (all warps already synced)
        if (it + 1 < NK)
            gemm_load_stage(stage0 + ((it + 1) & 1) * SM_AB_ELEMS, Ag, Bg, tid, (it + 1) * BK, D);

        const __nv_bfloat16* Ab = stage0 + (it & 1) * SM_AB_ELEMS;
        const __nv_bfloat16* Bb = Ab + BM * LDST;
#pragma unroll
        for (int ks = 0; ks < BK; ks += 16) {
            unsigned int af[4][4];
#pragma unroll
            for (int mt = 0; mt < 4; mt++) {
                int row = wm + mt * 16 + (lane & 15);
                int col = ks + ((lane >> 4) << 3);
                unsigned int addr = (unsigned int)__cvta_generic_to_shared(Ab + row * LDST + col);
                asm volatile("ldmatrix.sync.aligned.m8n8.x4.shared.b16 {%0,%1,%2,%3}, [%4];\n"
                             : "=r"(af[mt][0]), "=r"(af[mt][1]), "=r"(af[mt][2]), "=r"(af[mt][3])
                             : "r"(addr));
            }
            unsigned int bfg[8][2];
#pragma unroll
            for (int nt = 0; nt < 8; nt += 2) {
                // x4 over 16 n-rows x 16 k-cols:
                // m0=(rows nt,ks) m1=(rows nt+1,ks) m2=(rows nt,ks+8) m3=(rows nt+1,ks+8)
                int row = wn + nt * 8 + (lane & 15);
                int col = ks + ((lane >> 4) << 3);
                unsigned int addr = (unsigned int)__cvta_generic_to_shared(Bb + row * LDST + col);
                asm volatile("ldmatrix.sync.aligned.m8n8.x4.shared.b16 {%0,%1,%2,%3}, [%4];\n"
                             : "=r"(bfg[nt][0]), "=r"(bfg[nt + 1][0]),
                               "=r"(bfg[nt][1]), "=r"(bfg[nt + 1][1])
                             : "r"(addr));
            }
#pragma unroll
            for (int mt = 0; mt < 4; mt++)
#pragma unroll
                for (int nt = 0; nt < 8; nt++) {
                    asm volatile(
                        "mma.sync.aligned.m16n8k16.row.col.f32.bf16.bf16.f32 "
                        "{%0,%1,%2,%3}, {%4,%5,%6,%7}, {%8,%9}, {%0,%1,%2,%3};\n"
                        : "+f"(acc[mt][nt][0]), "+f"(acc[mt][nt][1]),
                          "+f"(acc[mt][nt][2]), "+f"(acc[mt][nt][3])
                        : "r"(af[mt][0]), "r"(af[mt][1]), "r"(af[mt][2]), "r"(af[mt][3]),
                          "r"(bfg[nt][0]), "r"(bfg[nt][1]));
                }
        }
        __syncthreads();
    }

    // ---- fused CE epilogue in accumulator layout ----
#pragma unroll
    for (int mt = 0; mt < 4; mt++) {
        int r0loc = wm + mt * 16 + (lane >> 2);
        int r1loc = r0loc + 8;
        int gr0 = rowBase + r0loc;
        int gr1 = rowBase + r1loc;
        int lab0 = labels[gr0]; lab0 = lab0 < 0 ? 0 : (lab0 >= C ? C - 1 : lab0);
        int lab1 = labels[gr1]; lab1 = lab1 < 0 ? 0 : (lab1 >= C ? C - 1 : lab1);
        float s0 = 0.f, t0 = 0.f, s1 = 0.f, t1 = 0.f;
#pragma unroll
        for (int nt = 0; nt < 8; nt++) {
            int c0loc = wn + nt * 8 + ((lane & 3) << 1);
            int c0 = colBase + c0loc;
            int c1 = c0 + 1;
            float bv0 = sBias[c0loc];
            float bv1 = sBias[c0loc + 1];
            if (c0 < C) {
                float l00 = acc[mt][nt][0] + bv0;
                float l10 = acc[mt][nt][2] + bv0;
                t0 += l00; s0 += fast_exp(l00);
                t1 += l10; s1 += fast_exp(l10);
                if (c0 == lab0) g_Z[gr0] = l00;
                if (c0 == lab1) g_Z[gr1] = l10;
            }
            if (c1 < C) {
                float l01 = acc[mt][nt][1] + bv1;
                float l11 = acc[mt][nt][3] + bv1;
                t0 += l01; s0 += fast_exp(l01);
                t1 += l11; s1 += fast_exp(l11);
                if (c1 == lab0) g_Z[gr0] = l01;
                if (c1 == lab1) g_Z[gr1] = l11;
            }
        }
        s0 += __shfl_xor_sync(0xffffffffu, s0, 1);
        s0 += __shfl_xor_sync(0xffffffffu, s0, 2);
        t0 += __shfl_xor_sync(0xffffffffu, t0, 1);
        t0 += __shfl_xor_sync(0xffffffffu, t0, 2);
        s1 += __shfl_xor_sync(0xffffffffu, s1, 1);
        s1 += __shfl_xor_sync(0xffffffffu, s1, 2);
        t1 += __shfl_xor_sync(0xffffffffu, t1, 1);
        t1 += __shfl_xor_sync(0xffffffffu, t1, 2);
        if ((lane & 3) == 0) {
            atomicAdd(&sS[r0loc], s0);
            atomicAdd(&sT[r0loc], t0);
            atomicAdd(&sS[r1loc], s1);
            atomicAdd(&sT[r1loc], t1);
        }
    }
    __syncthreads();
    // 128 threads, BM == 128: one row each
    atomicAdd(&g_S[rowBase + tid], sS[tid]);
    atomicAdd(&g_T[rowBase + tid], sT[tid]);
}

// total = moco + 0.5*(trip_m + trip_t)/B + mean_i[ log(S_i) - 0.9*Z_i - 0.1*T_i/C ]
__global__ void final_kernel(const float* __restrict__ moco, int B, int C,
                             float* __restrict__ out) {
    __shared__ double sh[256];
    double loc = 0.0;
    for (int i = threadIdx.x; i < B; i += 256) {
        loc += (double)logf(g_S[i]) - 0.9 * (double)g_Z[i]
             - (0.1 / (double)C) * (double)g_T[i];
    }
    sh[threadIdx.x] = loc;
    __syncthreads();
    for (int s = 128; s > 0; s >>= 1) {
        if (threadIdx.x < s) sh[threadIdx.x] += sh[threadIdx.x + s];
        __syncthreads();
    }
    if (threadIdx.x == 0) {
        double ce = sh[0] / (double)B;
        double total = (double)moco[0]
                     + 0.5 * ((double)g_trip[0] / (double)B + (double)g_trip[1] / (double)B)
                     + ce;
        out[0] = (float)total;
    }
}

// ---------------- launch ----------------
extern "C" void kernel_launch(void* const* d_in, const int* in_sizes, int n_in,
                              void* d_out, int out_size) {
    const float* F_mixed       = (const float*)d_in[0];
    const float* F_target      = (const float*)d_in[1];
    const float* F_source      = (const float*)d_in[2];
    const float* mixed_labels  = (const float*)d_in[3];
    const int*   pseudo_labels = (const int*)d_in[4];
    const int*   source_labels = (const int*)d_in[5];
    const float* moco = (const float*)d_in[7];
    const float* W    = (const float*)d_in[8];
    const float* b    = (const float*)d_in[9];
    float* out = (float*)d_out;

    int B = in_sizes[4];
    int C = in_sizes[9];
    int D = in_sizes[0] / B;

    cudaFuncSetAttribute(ce_gemm_mma, cudaFuncAttributeMaxDynamicSharedMemorySize, GEMM_SMEM);

    zero_kernel<<<(B + 255) / 256, 256>>>(B);
    normalize_kernel<<<dim3(B, 3), 128>>>(F_mixed, F_target, F_source, B, D);
    int total4 = (C * D) / 4;
    convw_kernel<<<(total4 + 255) / 256, 256>>>(W, total4);
    argmax_kernel<<<B, 256>>>(mixed_labels, C);
    pick2_kernel<<<B, 256>>>(0, (const int*)0, 1, B, C, 12345u);
    pick2_kernel<<<B, 256>>>(1, pseudo_labels, 0, B, C, 777777u);
    triplet_kernel<<<dim3(B, 2), 128>>>(B, D);
    dim3 gg((C + BN - 1) / BN, (B + BM - 1) / BM);
    ce_gemm_mma<<<gg, 128, GEMM_SMEM>>>(b, source_labels, B, C, D);
    final_kernel<<<1, 256>>>(moco, B, C, out);
    (void)n_in; (void)out_size;
}